// round 11
// baseline (speedup 1.0000x reference)
#include <cuda_runtime.h>
#include <cuda_bf16.h>
#include <cstdint>

// Problem constants (fixed): B=4, S=4096, H=1024, C=256
#define Hh 1024
#define Cc 256
#define ROWS_PER_TENSOR 16384
#define ROWS_TOTAL      32768
#define BM 64
#define NTILES (ROWS_TOTAL / BM)   // 512
#define KC 64
#define NCHUNK 16
#define NT 256
#define NCTA 296                   // 2 per SM, persistent
#define MARGIN 2.5f                // >= 2 * max plausible bf16 score error (rms ~0.1)
#define CAP 1024                   // per-code row-list capacity (avg 128)

// __device__ scratch (no allocation allowed)
__device__ __nv_bfloat16 g_chi[Cc * Hh];
__device__ float g_csq[Cc];
__device__ int   g_idx[ROWS_TOTAL];
__device__ unsigned char g_isflag[ROWS_TOTAL];
__device__ int   g_tick;
__device__ int   g_nflag;
__device__ int   g_ccount[Cc];
__device__ int   g_clist[Cc * CAP];
__device__ int   g_frow[ROWS_TOTAL];
__device__ int   g_fcnt[ROWS_TOTAL];
__device__ int   g_fcand[ROWS_TOTAL][8];

// ---------------- helpers ----------------
__device__ __forceinline__ uint32_t swz128(uint32_t off) {   // XOR bits[6:4] ^= bits[9:7]
    return off ^ ((off >> 3) & 0x70u);
}
__device__ __forceinline__ uint32_t smem_u32(const void* p) {
    uint32_t a;
    asm("{ .reg .u64 t; cvta.to.shared.u64 t, %1; cvt.u32.u64 %0, t; }" : "=r"(a) : "l"(p));
    return a;
}
__device__ __forceinline__ void cpa16(uint32_t dst, const void* src) {
    asm volatile("{ .reg .u64 g; cvta.to.global.u64 g, %1; "
                 "cp.async.cg.shared.global [%0], [g], 16; }"
                 :: "r"(dst), "l"(src) : "memory");
}
#define CP_COMMIT() asm volatile("cp.async.commit_group;" ::: "memory")
#define CP_WAIT0()  asm volatile("cp.async.wait_group 0;" ::: "memory")

__device__ __forceinline__ void ldsm4(uint32_t* r, uint32_t addr) {
    asm volatile("ldmatrix.sync.aligned.m8n8.x4.shared.b16 {%0,%1,%2,%3}, [%4];"
                 : "=r"(r[0]), "=r"(r[1]), "=r"(r[2]), "=r"(r[3]) : "r"(addr));
}
__device__ __forceinline__ void mma16816(float* d, const uint32_t* a, uint32_t b0, uint32_t b1) {
    asm volatile("mma.sync.aligned.m16n8k16.row.col.f32.bf16.bf16.f32 "
                 "{%0,%1,%2,%3}, {%4,%5,%6,%7}, {%8,%9}, {%0,%1,%2,%3};"
                 : "+f"(d[0]), "+f"(d[1]), "+f"(d[2]), "+f"(d[3])
                 : "r"(a[0]), "r"(a[1]), "r"(a[2]), "r"(a[3]), "r"(b0), "r"(b1));
}
// fp32x4 -> packed bf16 (RNE)
__device__ __forceinline__ void cvt4(const float4 v, uint32_t& h01, uint32_t& h23) {
    asm("cvt.rn.bf16x2.f32 %0, %1, %2;" : "=r"(h01) : "f"(v.y), "f"(v.x));
    asm("cvt.rn.bf16x2.f32 %0, %1, %2;" : "=r"(h23) : "f"(v.w), "f"(v.z));
}
// correctness-only fallback: one thread writes a full masked row
__device__ void direct_row_write(const float* cb, float* out, int row, int ci, float m) {
    const float4* cr = reinterpret_cast<const float4*>(cb + (size_t)ci * Hh);
    float4* orow = reinterpret_cast<float4*>(out + (size_t)row * Hh);
    for (int u = 0; u < Hh / 4; u++) {
        float4 v = cr[u];
        v.x *= m; v.y *= m; v.z *= m; v.w *= m;
        orow[u] = v;
    }
}

// ---------------- Kernel 1: codebook bf16 + norms + counter reset ----------
__global__ void prep_kernel(const float* __restrict__ cb) {
    const int c = blockIdx.x;
    const int t = threadIdx.x;                 // 256 threads, one float4 each
    if (c == 0 && t == 0) { g_nflag = 0; g_tick = 0; }
    if (t == 0) g_ccount[c] = 0;
    float4 v = reinterpret_cast<const float4*>(cb + (size_t)c * Hh)[t];
    float s = v.x * v.x + v.y * v.y + v.z * v.z + v.w * v.w;
    uint32_t h01, h23;
    cvt4(v, h01, h23);
    reinterpret_cast<uint2*>(g_chi + (size_t)c * Hh)[t] = make_uint2(h01, h23);
#pragma unroll
    for (int o = 16; o > 0; o >>= 1) s += __shfl_xor_sync(0xffffffffu, s, o);
    __shared__ float ws[8];
    if ((t & 31) == 0) ws[t >> 5] = s;
    __syncthreads();
    if (t == 0) {
        float tot = 0.f;
#pragma unroll
        for (int i = 0; i < 8; i++) tot += ws[i];
        g_csq[c] = tot;
    }
}

// ------- Kernel 2: persistent ticketed mma.sync GEMM + argmin (indices) ----
// smem per stage: A 64x64 bf16 = 8K | B 256x64 bf16 = 32K
#define STG 40960
#define OFF_A(s) ((s) * STG + 0)
#define OFF_B(s) ((s) * STG + 8192)
#define OFF_CSQ   81920
#define OFF_BV    82944
#define OFF_BI    83968
#define OFF_RMIN  84992
#define OFF_CNT   85248
#define OFF_CAND  85504
#define OFF_TILE  87552
#define SMEM_TOTAL 87680

__global__ __launch_bounds__(NT, 2)
void vq_gemm(const float* __restrict__ keys, const float* __restrict__ values) {
    extern __shared__ __align__(1024) char smem[];
    const uint32_t sb = smem_u32(smem);
    const int tid  = threadIdx.x;
    const int lane = tid & 31;
    const int wid  = tid >> 5;          // 0..7
    const int wm   = wid >> 2;          // 0..1 (M)
    const int wn   = wid & 3;           // 0..3 (N)

    if (tid < Cc) reinterpret_cast<float*>(smem + OFF_CSQ)[tid] = g_csq[tid];

    const float* csq = reinterpret_cast<const float*>(smem + OFF_CSQ);
    float* bvs   = reinterpret_cast<float*>(smem + OFF_BV);
    int*   bis   = reinterpret_cast<int*>(smem + OFF_BI);
    float* rminv = reinterpret_cast<float*>(smem + OFF_RMIN);
    int*   cnt_s = reinterpret_cast<int*>(smem + OFF_CNT);
    int*   cand  = reinterpret_cast<int*>(smem + OFF_CAND);
    volatile int* tshare = reinterpret_cast<volatile int*>(smem + OFF_TILE);

    const int aRowB = (wm * 32 + (lane & 15)) * 128;              // + mt*2048
    const int aColB = (lane >> 4) * 16;
    const int bRow  = wn * 64 + ((lane >> 4) << 3) + (lane & 7);  // + p*16
    const int bColB = ((lane >> 3) & 1) * 16;

    while (true) {
        if (tid == 0) *tshare = atomicAdd(&g_tick, 1);
        if (tid < BM) cnt_s[tid] = 0;
        __syncthreads();
        const int tile = *tshare;
        if (tile >= NTILES) break;
        const int rowBase = tile * BM;

        const float* src_base; int srcRow;
        if (rowBase < ROWS_PER_TENSOR) { src_base = keys;   srcRow = rowBase; }
        else                           { src_base = values; srcRow = rowBase - ROWS_PER_TENSOR; }

        float acc[2][8][4];
#pragma unroll
        for (int a = 0; a < 2; a++)
#pragma unroll
            for (int b = 0; b < 8; b++)
#pragma unroll
                for (int k = 0; k < 4; k++) acc[a][b][k] = 0.f;

        auto loadB = [&](int c, int s) {     // 256x64 bf16 = 2048 16B units, 8/thread
#pragma unroll
            for (int i = 0; i < 8; i++) {
                int li = tid + i * NT;
                int row = li >> 3, u = li & 7;
                const __nv_bfloat16* gh = g_chi + (size_t)row * Hh + c * KC + u * 8;
                uint32_t off = swz128((uint32_t)(row * 128 + u * 16));
                cpa16(sb + OFF_B(s) + off, gh);
            }
        };
        auto loadA = [&](float4* pf, int c) {  // 64x64 fp32 = 1024 float4, 4/thread
#pragma unroll
            for (int i = 0; i < 4; i++) {
                int li = tid + i * NT;
                int row = li >> 4, u = li & 15;
                pf[i] = *reinterpret_cast<const float4*>(
                    src_base + (size_t)(srcRow + row) * Hh + c * KC + u * 4);
            }
        };
        auto storeA = [&](const float4* pf, int s) {
#pragma unroll
            for (int i = 0; i < 4; i++) {
                int li = tid + i * NT;
                int row = li >> 4, u = li & 15;
                uint32_t h01, h23;
                cvt4(pf[i], h01, h23);
                uint32_t off = swz128((uint32_t)(row * 128 + u * 8));
                *reinterpret_cast<uint2*>(smem + OFF_A(s) + off) = make_uint2(h01, h23);
            }
        };

        float4 pf[4];
        loadB(0, 0); CP_COMMIT();
        loadA(pf, 0);
        storeA(pf, 0);
        CP_WAIT0();
        __syncthreads();

        for (int c = 0; c < NCHUNK; c++) {
            const int s = c & 1;
            if (c + 1 < NCHUNK) { loadB(c + 1, s ^ 1); CP_COMMIT(); loadA(pf, c + 1); }

            const uint32_t aS = sb + OFF_A(s), bS = sb + OFF_B(s);
#pragma unroll
            for (int ks = 0; ks < 4; ks++) {
                uint32_t ah[2][4];
#pragma unroll
                for (int mt = 0; mt < 2; mt++)
                    ldsm4(ah[mt], aS + swz128((uint32_t)(aRowB + mt * 2048 + ks * 32 + aColB)));
#pragma unroll
                for (int p = 0; p < 4; p++) {
                    uint32_t bh[4];
                    ldsm4(bh, bS + swz128((uint32_t)((bRow + p * 16) * 128 + ks * 32 + bColB)));
#pragma unroll
                    for (int mt = 0; mt < 2; mt++) {
                        mma16816(acc[mt][2 * p],     ah[mt], bh[0], bh[1]);
                        mma16816(acc[mt][2 * p + 1], ah[mt], bh[2], bh[3]);
                    }
                }
            }
            if (c + 1 < NCHUNK) { storeA(pf, s ^ 1); CP_WAIT0(); }
            __syncthreads();
        }

        // ---- epilogue: scores, per-row argmin, candidates; indices to global ----
        float mv[4]; int mi[4];
#pragma unroll
        for (int q = 0; q < 4; q++) { mv[q] = __int_as_float(0x7f800000); mi[q] = 0x7fffffff; }
#pragma unroll
        for (int mt = 0; mt < 2; mt++)
#pragma unroll
            for (int nt = 0; nt < 8; nt++) {
                int n0 = wn * 64 + nt * 8 + (lane & 3) * 2;
                float cq0 = csq[n0], cq1 = csq[n0 + 1];
                float s0 = cq0 - 2.f * acc[mt][nt][0];
                float s1 = cq1 - 2.f * acc[mt][nt][1];
                float s2 = cq0 - 2.f * acc[mt][nt][2];
                float s3 = cq1 - 2.f * acc[mt][nt][3];
                int q0 = mt * 2, q1 = mt * 2 + 1;
                if (s0 < mv[q0]) { mv[q0] = s0; mi[q0] = n0; }
                if (s1 < mv[q0]) { mv[q0] = s1; mi[q0] = n0 + 1; }
                if (s2 < mv[q1]) { mv[q1] = s2; mi[q1] = n0; }
                if (s3 < mv[q1]) { mv[q1] = s3; mi[q1] = n0 + 1; }
            }
#pragma unroll
        for (int o = 1; o < 4; o <<= 1)
#pragma unroll
            for (int q = 0; q < 4; q++) {
                float ov = __shfl_xor_sync(0xffffffffu, mv[q], o);
                int   oi = __shfl_xor_sync(0xffffffffu, mi[q], o);
                if (ov < mv[q] || (ov == mv[q] && oi < mi[q])) { mv[q] = ov; mi[q] = oi; }
            }
        if ((lane & 3) == 0) {
#pragma unroll
            for (int q = 0; q < 4; q++) {
                int r = wm * 32 + (q >> 1) * 16 + (lane >> 2) + (q & 1) * 8;
                bvs[r * 4 + wn] = mv[q];
                bis[r * 4 + wn] = mi[q];
            }
        }
        __syncthreads();
        if (tid < BM) {
            float bv = bvs[tid * 4]; int bi = bis[tid * 4];
#pragma unroll
            for (int w = 1; w < 4; w++) {
                float v = bvs[tid * 4 + w]; int i = bis[tid * 4 + w];
                if (v < bv || (v == bv && i < bi)) { bv = v; bi = i; }
            }
            rminv[tid] = bv;
            g_idx[rowBase + tid] = bi;     // provisional (fixup may overwrite)
        }
        __syncthreads();
        // candidate scan: any score within MARGIN of the row min -> exact recheck
#pragma unroll
        for (int mt = 0; mt < 2; mt++) {
            int rA = wm * 32 + mt * 16 + (lane >> 2);
            float thA = rminv[rA] + MARGIN;
            float thB = rminv[rA + 8] + MARGIN;
#pragma unroll
            for (int nt = 0; nt < 8; nt++) {
                int n0 = wn * 64 + nt * 8 + (lane & 3) * 2;
                float cq0 = csq[n0], cq1 = csq[n0 + 1];
                float s0 = cq0 - 2.f * acc[mt][nt][0];
                float s1 = cq1 - 2.f * acc[mt][nt][1];
                float s2 = cq0 - 2.f * acc[mt][nt][2];
                float s3 = cq1 - 2.f * acc[mt][nt][3];
                if (s0 <= thA) { int p = atomicAdd(&cnt_s[rA], 1);     if (p < 8) cand[rA * 8 + p] = n0; }
                if (s1 <= thA) { int p = atomicAdd(&cnt_s[rA], 1);     if (p < 8) cand[rA * 8 + p] = n0 + 1; }
                if (s2 <= thB) { int p = atomicAdd(&cnt_s[rA + 8], 1); if (p < 8) cand[(rA + 8) * 8 + p] = n0; }
                if (s3 <= thB) { int p = atomicAdd(&cnt_s[rA + 8], 1); if (p < 8) cand[(rA + 8) * 8 + p] = n0 + 1; }
            }
        }
        __syncthreads();
        if (tid < BM) {
            bool fl = (cnt_s[tid] > 1);     // ambiguous under bf16 noise
            g_isflag[rowBase + tid] = fl ? 1 : 0;
            if (fl) {
                int gi = atomicAdd(&g_nflag, 1);
                g_frow[gi] = rowBase + tid;
                int cc = cnt_s[tid] <= 8 ? cnt_s[tid] : 0;   // 0 => recompute all 256
                g_fcnt[gi] = cc;
                for (int j = 0; j < cc; j++) g_fcand[gi][j] = cand[tid * 8 + j];
            }
        }
        __syncthreads();   // protect cnt_s/cand/rminv reuse by next tile
    }
}

// ------ Kernel 3: exact fixup for flagged rows + per-code row lists --------
__global__ void fixlist_kernel(const float* __restrict__ keys, const float* __restrict__ values,
                               const float* __restrict__ cb, float* __restrict__ out) {
    const int gtid    = blockIdx.x * blockDim.x + threadIdx.x;
    const int gstride = gridDim.x * blockDim.x;
    const int lane    = threadIdx.x & 31;
    const int warp    = gtid >> 5;
    const int nwarp   = gstride >> 5;

    // Phase 1: elementwise scatter of unflagged rows into per-code lists.
    for (int i = gtid; i < ROWS_TOTAL; i += gstride) {
        if (!g_isflag[i]) {
            int c = g_idx[i];
            int p = atomicAdd(&g_ccount[c], 1);
            if (p < CAP) g_clist[c * CAP + p] = i;
            else {  // statistically never: overflow -> direct correct write
                float m = (g_csq[c] > 0.01f) ? 1.0f : 0.0f;
                direct_row_write(cb, out, i, c, m);
            }
        }
    }

    // Phase 2: warp per flagged row: exact fp32 argmin, then scatter.
    const int nflag = g_nflag;
    for (int e = warp; e < nflag; e += nwarp) {
        int row = g_frow[e];
        int cc  = g_fcnt[e];
        const float4* xr = reinterpret_cast<const float4*>(
            row < ROWS_PER_TENSOR ? keys + (size_t)row * Hh
                                  : values + (size_t)(row - ROWS_PER_TENSOR) * Hh);
        float4 xa[8];
#pragma unroll
        for (int t = 0; t < 8; t++) xa[t] = xr[lane + 32 * t];
        int ncand = (cc == 0) ? Cc : cc;
        float bv = __int_as_float(0x7f800000);
        int   bi = 0x7fffffff;
        for (int j = 0; j < ncand; j++) {
            int c = (cc == 0) ? j : g_fcand[e][j];
            const float4* cr = reinterpret_cast<const float4*>(cb + (size_t)c * Hh);
            float d = 0.f;
#pragma unroll
            for (int t = 0; t < 8; t++) {
                float4 b = cr[lane + 32 * t];
                d += xa[t].x * b.x + xa[t].y * b.y + xa[t].z * b.z + xa[t].w * b.w;
            }
#pragma unroll
            for (int o = 16; o > 0; o >>= 1) d += __shfl_xor_sync(0xffffffffu, d, o);
            float sc = g_csq[c] - 2.f * d;
            if (sc < bv || (sc == bv && c < bi)) { bv = sc; bi = c; }
        }
        if (lane == 0) {
            g_idx[row] = bi;
            int p = atomicAdd(&g_ccount[bi], 1);
            if (p < CAP) g_clist[bi * CAP + p] = row;
            else {
                float m = (g_csq[bi] > 0.01f) ? 1.0f : 0.0f;
                direct_row_write(cb, out, row, bi, m);
            }
        }
    }
}

// ---------------- Kernel 4: scatter writeback (write-only traffic) ---------
// Block (c, part): code row held in registers, streamed to all its rows.
#define WB_PARTS 4
__global__ __launch_bounds__(256, 8)
void wb_kernel(const float* __restrict__ cb, float* __restrict__ out) {
    const int c    = blockIdx.x & (Cc - 1);
    const int part = blockIdx.x >> 8;
    const int t    = threadIdx.x;
    int n = g_ccount[c];
    if (n > CAP) n = CAP;
    const float m = (g_csq[c] > 0.01f) ? 1.0f : 0.0f;   // ||c|| > 0.1
    float4 v = __ldg(reinterpret_cast<const float4*>(cb + (size_t)c * Hh) + t);
    v.x *= m; v.y *= m; v.z *= m; v.w *= m;
    const int* lst = g_clist + c * CAP;
    for (int j = part; j < n; j += WB_PARTS) {
        int row = __ldg(&lst[j]);
        __stcs(reinterpret_cast<float4*>(out + (size_t)row * Hh) + t, v);
    }
}

extern "C" void kernel_launch(void* const* d_in, const int* in_sizes, int n_in,
                              void* d_out, int out_size) {
    const float* keys     = (const float*)d_in[0];
    const float* values   = (const float*)d_in[1];
    const float* codebook = (const float*)d_in[2];
    float* out = (float*)d_out;

    cudaFuncSetAttribute(vq_gemm, cudaFuncAttributeMaxDynamicSharedMemorySize, SMEM_TOTAL);
    prep_kernel<<<Cc, 256>>>(codebook);
    vq_gemm<<<NCTA, NT, SMEM_TOTAL>>>(keys, values);
    fixlist_kernel<<<148, 256>>>(keys, values, codebook, out);
    wb_kernel<<<Cc * WB_PARTS, 256>>>(codebook, out);
}

// round 12
// speedup vs baseline: 2.4152x; 2.4152x over previous
#include <cuda_runtime.h>
#include <cuda_bf16.h>
#include <cstdint>

// Problem constants (fixed): B=4, S=4096, H=1024, C=256
#define Hh 1024
#define Cc 256
#define ROWS_PER_TENSOR 16384
#define ROWS_TOTAL      32768
#define BM 128
#define NTILES (ROWS_TOTAL / BM)   // 256
#define KC 64
#define NCHUNK 16
#define NT 512
#define NCTA 148                   // 1 per SM, persistent
#define MARGIN 2.5f                // >= 2 * max plausible bf16 score error (rms ~0.1)

// __device__ scratch (no allocation allowed)
__device__ __nv_bfloat16 g_chi[Cc * Hh];
__device__ float g_csq[Cc];
__device__ int   g_idx[ROWS_TOTAL];
__device__ int   g_tick;
__device__ int   g_nflag;
__device__ int   g_frow[ROWS_TOTAL];
__device__ int   g_fcnt[ROWS_TOTAL];
__device__ int   g_fcand[ROWS_TOTAL][8];

// ---------------- helpers ----------------
__device__ __forceinline__ uint32_t swz128(uint32_t off) {   // XOR bits[6:4] ^= bits[9:7]
    return off ^ ((off >> 3) & 0x70u);
}
__device__ __forceinline__ uint32_t smem_u32(const void* p) {
    uint32_t a;
    asm("{ .reg .u64 t; cvta.to.shared.u64 t, %1; cvt.u32.u64 %0, t; }" : "=r"(a) : "l"(p));
    return a;
}
__device__ __forceinline__ void cpa16(uint32_t dst, const void* src) {
    asm volatile("{ .reg .u64 g; cvta.to.global.u64 g, %1; "
                 "cp.async.cg.shared.global [%0], [g], 16; }"
                 :: "r"(dst), "l"(src) : "memory");
}
#define CP_COMMIT() asm volatile("cp.async.commit_group;" ::: "memory")
#define CP_WAIT0()  asm volatile("cp.async.wait_group 0;" ::: "memory")

__device__ __forceinline__ void ldsm4(uint32_t* r, uint32_t addr) {
    asm volatile("ldmatrix.sync.aligned.m8n8.x4.shared.b16 {%0,%1,%2,%3}, [%4];"
                 : "=r"(r[0]), "=r"(r[1]), "=r"(r[2]), "=r"(r[3]) : "r"(addr));
}
__device__ __forceinline__ void mma16816(float* d, const uint32_t* a, uint32_t b0, uint32_t b1) {
    asm volatile("mma.sync.aligned.m16n8k16.row.col.f32.bf16.bf16.f32 "
                 "{%0,%1,%2,%3}, {%4,%5,%6,%7}, {%8,%9}, {%0,%1,%2,%3};"
                 : "+f"(d[0]), "+f"(d[1]), "+f"(d[2]), "+f"(d[3])
                 : "r"(a[0]), "r"(a[1]), "r"(a[2]), "r"(a[3]), "r"(b0), "r"(b1));
}
// fp32x4 -> packed bf16 (RNE)
__device__ __forceinline__ void cvt4(const float4 v, uint32_t& h01, uint32_t& h23) {
    asm("cvt.rn.bf16x2.f32 %0, %1, %2;" : "=r"(h01) : "f"(v.y), "f"(v.x));
    asm("cvt.rn.bf16x2.f32 %0, %1, %2;" : "=r"(h23) : "f"(v.w), "f"(v.z));
}

// ---------------- Kernel 1: codebook bf16 + norms + counter reset ----------
__global__ void prep_kernel(const float* __restrict__ cb) {
    const int c = blockIdx.x;
    const int t = threadIdx.x;                 // 256 threads, one float4 each
    if (c == 0 && t == 0) { g_nflag = 0; g_tick = 0; }
    float4 v = reinterpret_cast<const float4*>(cb + (size_t)c * Hh)[t];
    float s = v.x * v.x + v.y * v.y + v.z * v.z + v.w * v.w;
    uint32_t h01, h23;
    cvt4(v, h01, h23);
    reinterpret_cast<uint2*>(g_chi + (size_t)c * Hh)[t] = make_uint2(h01, h23);
#pragma unroll
    for (int o = 16; o > 0; o >>= 1) s += __shfl_xor_sync(0xffffffffu, s, o);
    __shared__ float ws[8];
    if ((t & 31) == 0) ws[t >> 5] = s;
    __syncthreads();
    if (t == 0) {
        float tot = 0.f;
#pragma unroll
        for (int i = 0; i < 8; i++) tot += ws[i];
        g_csq[c] = tot;
    }
}

// ------- Kernel 2: persistent ticketed mma.sync GEMM + argmin (indices) ----
// smem per stage: A 128x64 bf16 = 16K | B 256x64 bf16 = 32K
#define STG 49152
#define OFF_A(s) ((s) * STG + 0)
#define OFF_B(s) ((s) * STG + 16384)
#define OFF_CSQ    98304
#define OFF_BV     99328
#define OFF_BI    101376
#define OFF_RMIN  103424
#define OFF_CNT   103936
#define OFF_CAND  104448
#define OFF_TILE  108544
#define SMEM_TOTAL 108672

__global__ __launch_bounds__(NT, 1)
void vq_gemm(const float* __restrict__ keys, const float* __restrict__ values) {
    extern __shared__ __align__(1024) char smem[];
    const uint32_t sb = smem_u32(smem);
    const int tid  = threadIdx.x;
    const int lane = tid & 31;
    const int wid  = tid >> 5;          // 0..15
    const int wm   = wid >> 2;          // 0..3 (M)
    const int wn   = wid & 3;           // 0..3 (N)

    if (tid < Cc) reinterpret_cast<float*>(smem + OFF_CSQ)[tid] = g_csq[tid];

    const float* csq = reinterpret_cast<const float*>(smem + OFF_CSQ);
    float* bvs   = reinterpret_cast<float*>(smem + OFF_BV);
    int*   bis   = reinterpret_cast<int*>(smem + OFF_BI);
    float* rminv = reinterpret_cast<float*>(smem + OFF_RMIN);
    int*   cnt_s = reinterpret_cast<int*>(smem + OFF_CNT);
    int*   cand  = reinterpret_cast<int*>(smem + OFF_CAND);
    volatile int* tshare = reinterpret_cast<volatile int*>(smem + OFF_TILE);

    const int aRowB = (wm * 32 + (lane & 15)) * 128;              // + mt*2048
    const int aColB = (lane >> 4) * 16;
    const int bRow  = wn * 64 + ((lane >> 4) << 3) + (lane & 7);  // + p*16
    const int bColB = ((lane >> 3) & 1) * 16;

    while (true) {
        if (tid == 0) *tshare = atomicAdd(&g_tick, 1);
        if (tid < BM) cnt_s[tid] = 0;
        __syncthreads();
        const int tile = *tshare;
        if (tile >= NTILES) break;
        const int rowBase = tile * BM;

        const float* src_base; int srcRow;
        if (rowBase < ROWS_PER_TENSOR) { src_base = keys;   srcRow = rowBase; }
        else                           { src_base = values; srcRow = rowBase - ROWS_PER_TENSOR; }

        float acc[2][8][4];
#pragma unroll
        for (int a = 0; a < 2; a++)
#pragma unroll
            for (int b = 0; b < 8; b++)
#pragma unroll
                for (int k = 0; k < 4; k++) acc[a][b][k] = 0.f;

        auto loadB = [&](int c, int s) {     // 256x64 bf16 = 2048 16B units, 4/thread
#pragma unroll
            for (int i = 0; i < 4; i++) {
                int li = tid + i * NT;
                int row = li >> 3, u = li & 7;
                const __nv_bfloat16* gh = g_chi + (size_t)row * Hh + c * KC + u * 8;
                uint32_t off = swz128((uint32_t)(row * 128 + u * 16));
                cpa16(sb + OFF_B(s) + off, gh);
            }
        };
        auto loadA = [&](float4* pf, int c) {  // 128x64 fp32 = 2048 float4, 4/thread
#pragma unroll
            for (int i = 0; i < 4; i++) {
                int li = tid + i * NT;
                int row = li >> 4, u = li & 15;
                pf[i] = *reinterpret_cast<const float4*>(
                    src_base + (size_t)(srcRow + row) * Hh + c * KC + u * 4);
            }
        };
        auto storeA = [&](const float4* pf, int s) {
#pragma unroll
            for (int i = 0; i < 4; i++) {
                int li = tid + i * NT;
                int row = li >> 4, u = li & 15;
                uint32_t h01, h23;
                cvt4(pf[i], h01, h23);
                uint32_t off = swz128((uint32_t)(row * 128 + u * 8));
                *reinterpret_cast<uint2*>(smem + OFF_A(s) + off) = make_uint2(h01, h23);
            }
        };

        float4 pf[4];
        loadB(0, 0); CP_COMMIT();
        loadA(pf, 0);
        storeA(pf, 0);
        CP_WAIT0();
        __syncthreads();

        for (int c = 0; c < NCHUNK; c++) {
            const int s = c & 1;
            if (c + 1 < NCHUNK) { loadB(c + 1, s ^ 1); CP_COMMIT(); loadA(pf, c + 1); }

            const uint32_t aS = sb + OFF_A(s), bS = sb + OFF_B(s);
#pragma unroll
            for (int ks = 0; ks < 4; ks++) {
                uint32_t ah[2][4];
#pragma unroll
                for (int mt = 0; mt < 2; mt++)
                    ldsm4(ah[mt], aS + swz128((uint32_t)(aRowB + mt * 2048 + ks * 32 + aColB)));
#pragma unroll
                for (int p = 0; p < 4; p++) {
                    uint32_t bh[4];
                    ldsm4(bh, bS + swz128((uint32_t)((bRow + p * 16) * 128 + ks * 32 + bColB)));
#pragma unroll
                    for (int mt = 0; mt < 2; mt++) {
                        mma16816(acc[mt][2 * p],     ah[mt], bh[0], bh[1]);
                        mma16816(acc[mt][2 * p + 1], ah[mt], bh[2], bh[3]);
                    }
                }
            }
            if (c + 1 < NCHUNK) { storeA(pf, s ^ 1); CP_WAIT0(); }
            __syncthreads();
        }

        // ---- epilogue: scores, per-row argmin, candidates; indices to global ----
        float mv[4]; int mi[4];
#pragma unroll
        for (int q = 0; q < 4; q++) { mv[q] = __int_as_float(0x7f800000); mi[q] = 0x7fffffff; }
#pragma unroll
        for (int mt = 0; mt < 2; mt++)
#pragma unroll
            for (int nt = 0; nt < 8; nt++) {
                int n0 = wn * 64 + nt * 8 + (lane & 3) * 2;
                float cq0 = csq[n0], cq1 = csq[n0 + 1];
                float s0 = cq0 - 2.f * acc[mt][nt][0];
                float s1 = cq1 - 2.f * acc[mt][nt][1];
                float s2 = cq0 - 2.f * acc[mt][nt][2];
                float s3 = cq1 - 2.f * acc[mt][nt][3];
                int q0 = mt * 2, q1 = mt * 2 + 1;
                if (s0 < mv[q0]) { mv[q0] = s0; mi[q0] = n0; }
                if (s1 < mv[q0]) { mv[q0] = s1; mi[q0] = n0 + 1; }
                if (s2 < mv[q1]) { mv[q1] = s2; mi[q1] = n0; }
                if (s3 < mv[q1]) { mv[q1] = s3; mi[q1] = n0 + 1; }
            }
#pragma unroll
        for (int o = 1; o < 4; o <<= 1)
#pragma unroll
            for (int q = 0; q < 4; q++) {
                float ov = __shfl_xor_sync(0xffffffffu, mv[q], o);
                int   oi = __shfl_xor_sync(0xffffffffu, mi[q], o);
                if (ov < mv[q] || (ov == mv[q] && oi < mi[q])) { mv[q] = ov; mi[q] = oi; }
            }
        if ((lane & 3) == 0) {
#pragma unroll
            for (int q = 0; q < 4; q++) {
                int r = wm * 32 + (q >> 1) * 16 + (lane >> 2) + (q & 1) * 8;
                bvs[r * 4 + wn] = mv[q];
                bis[r * 4 + wn] = mi[q];
            }
        }
        __syncthreads();
        if (tid < BM) {
            float bv = bvs[tid * 4]; int bi = bis[tid * 4];
#pragma unroll
            for (int w = 1; w < 4; w++) {
                float v = bvs[tid * 4 + w]; int i = bis[tid * 4 + w];
                if (v < bv || (v == bv && i < bi)) { bv = v; bi = i; }
            }
            rminv[tid] = bv;
            g_idx[rowBase + tid] = bi;     // provisional (fixup may overwrite)
        }
        __syncthreads();
        // candidate scan: any score within MARGIN of the row min -> exact recheck
#pragma unroll
        for (int mt = 0; mt < 2; mt++) {
            int rA = wm * 32 + mt * 16 + (lane >> 2);
            float thA = rminv[rA] + MARGIN;
            float thB = rminv[rA + 8] + MARGIN;
#pragma unroll
            for (int nt = 0; nt < 8; nt++) {
                int n0 = wn * 64 + nt * 8 + (lane & 3) * 2;
                float cq0 = csq[n0], cq1 = csq[n0 + 1];
                float s0 = cq0 - 2.f * acc[mt][nt][0];
                float s1 = cq1 - 2.f * acc[mt][nt][1];
                float s2 = cq0 - 2.f * acc[mt][nt][2];
                float s3 = cq1 - 2.f * acc[mt][nt][3];
                if (s0 <= thA) { int p = atomicAdd(&cnt_s[rA], 1);     if (p < 8) cand[rA * 8 + p] = n0; }
                if (s1 <= thA) { int p = atomicAdd(&cnt_s[rA], 1);     if (p < 8) cand[rA * 8 + p] = n0 + 1; }
                if (s2 <= thB) { int p = atomicAdd(&cnt_s[rA + 8], 1); if (p < 8) cand[(rA + 8) * 8 + p] = n0; }
                if (s3 <= thB) { int p = atomicAdd(&cnt_s[rA + 8], 1); if (p < 8) cand[(rA + 8) * 8 + p] = n0 + 1; }
            }
        }
        __syncthreads();
        if (tid < BM && cnt_s[tid] > 1) {   // ambiguous under bf16 noise -> exact fixup
            int gi = atomicAdd(&g_nflag, 1);
            g_frow[gi] = rowBase + tid;
            int cc = cnt_s[tid] <= 8 ? cnt_s[tid] : 0;   // 0 => recompute all 256
            g_fcnt[gi] = cc;
            for (int j = 0; j < cc; j++) g_fcand[gi][j] = cand[tid * 8 + j];
        }
        __syncthreads();   // protect cnt_s/cand/rminv reuse by next tile
    }
}

// ---------------- Kernel 3: exact fp32 index fixup for flagged rows --------
__global__ void fixup_kernel(const float* __restrict__ keys, const float* __restrict__ values,
                             const float* __restrict__ cb) {
    const int nflag = g_nflag;
    const int lane  = threadIdx.x & 31;
    const int warp  = (blockIdx.x * blockDim.x + threadIdx.x) >> 5;
    const int nwarp = (gridDim.x * blockDim.x) >> 5;

    for (int e = warp; e < nflag; e += nwarp) {
        int row = g_frow[e];
        int cc  = g_fcnt[e];
        const float4* xr = reinterpret_cast<const float4*>(
            row < ROWS_PER_TENSOR ? keys + (size_t)row * Hh
                                  : values + (size_t)(row - ROWS_PER_TENSOR) * Hh);
        float4 xa[8];
#pragma unroll
        for (int t = 0; t < 8; t++) xa[t] = xr[lane + 32 * t];
        int ncand = (cc == 0) ? Cc : cc;
        float bv = __int_as_float(0x7f800000);
        int   bi = 0x7fffffff;
        for (int j = 0; j < ncand; j++) {
            int c = (cc == 0) ? j : g_fcand[e][j];
            const float4* cr = reinterpret_cast<const float4*>(cb + (size_t)c * Hh);
            float d = 0.f;
#pragma unroll
            for (int t = 0; t < 8; t++) {
                float4 b = cr[lane + 32 * t];
                d += xa[t].x * b.x + xa[t].y * b.y + xa[t].z * b.z + xa[t].w * b.w;
            }
#pragma unroll
            for (int o = 16; o > 0; o >>= 1) d += __shfl_xor_sync(0xffffffffu, d, o);
            float sc = g_csq[c] - 2.f * d;
            if (sc < bv || (sc == bv && c < bi)) { bv = sc; bi = c; }
        }
        if (lane == 0) g_idx[row] = bi;
    }
}

// ---------------- Kernel 4: pure gather + masked writeback -----------------
// Grid-stride: 2048 blocks x 256 threads, one row per block-iteration,
// next-row index prefetched to hide the idx->codebook load chain.
#define WB_BLOCKS 2048
__global__ __launch_bounds__(256, 8)
void wb_kernel(const float* __restrict__ cb, float* __restrict__ out) {
    const int t = threadIdx.x;
    int row = blockIdx.x;
    int ci  = __ldg(&g_idx[row]);
    while (true) {
        int nrow = row + WB_BLOCKS;
        int nci  = (nrow < ROWS_TOTAL) ? __ldg(&g_idx[nrow]) : 0;
        const float m = (__ldg(&g_csq[ci]) > 0.01f) ? 1.0f : 0.0f;   // ||c|| > 0.1
        float4 v = __ldg(reinterpret_cast<const float4*>(cb + (size_t)ci * Hh) + t);
        v.x *= m; v.y *= m; v.z *= m; v.w *= m;
        __stcs(reinterpret_cast<float4*>(out + (size_t)row * Hh) + t, v);
        if (nrow >= ROWS_TOTAL) break;
        row = nrow; ci = nci;
    }
}

extern "C" void kernel_launch(void* const* d_in, const int* in_sizes, int n_in,
                              void* d_out, int out_size) {
    const float* keys     = (const float*)d_in[0];
    const float* values   = (const float*)d_in[1];
    const float* codebook = (const float*)d_in[2];
    float* out = (float*)d_out;

    cudaFuncSetAttribute(vq_gemm, cudaFuncAttributeMaxDynamicSharedMemorySize, SMEM_TOTAL);
    prep_kernel<<<Cc, 256>>>(codebook);
    vq_gemm<<<NCTA, NT, SMEM_TOTAL>>>(keys, values);
    fixup_kernel<<<148, 256>>>(keys, values, codebook);
    wb_kernel<<<WB_BLOCKS, 256>>>(codebook, out);
}

// round 13
// speedup vs baseline: 2.4671x; 1.0215x over previous
#include <cuda_runtime.h>
#include <cuda_bf16.h>
#include <cstdint>

// Problem constants (fixed): B=4, S=4096, H=1024, C=256
#define Hh 1024
#define Cc 256
#define ROWS_PER_TENSOR 16384
#define ROWS_TOTAL      32768
#define BM 64
#define NTILES (ROWS_TOTAL / BM)   // 512
#define KC 64
#define NCHUNK 16
#define NT 256
#define NCTA 296                   // 2 per SM, persistent
#define MARGIN 2.5f                // >= 2 * max plausible bf16 score error (rms ~0.1)

// __device__ scratch (no allocation allowed)
__device__ __nv_bfloat16 g_chi[Cc * Hh];
__device__ float g_csq[Cc];
__device__ int   g_tick;
__device__ int   g_nflag;
__device__ int   g_frow[ROWS_TOTAL];
__device__ int   g_fcnt[ROWS_TOTAL];
__device__ int   g_fcand[ROWS_TOTAL][8];

// ---------------- helpers ----------------
__device__ __forceinline__ uint32_t swz128(uint32_t off) {   // XOR bits[6:4] ^= bits[9:7]
    return off ^ ((off >> 3) & 0x70u);
}
__device__ __forceinline__ uint32_t smem_u32(const void* p) {
    uint32_t a;
    asm("{ .reg .u64 t; cvta.to.shared.u64 t, %1; cvt.u32.u64 %0, t; }" : "=r"(a) : "l"(p));
    return a;
}
__device__ __forceinline__ void cpa16(uint32_t dst, const void* src) {
    asm volatile("{ .reg .u64 g; cvta.to.global.u64 g, %1; "
                 "cp.async.cg.shared.global [%0], [g], 16; }"
                 :: "r"(dst), "l"(src) : "memory");
}
#define CP_COMMIT() asm volatile("cp.async.commit_group;" ::: "memory")
#define CP_WAIT0()  asm volatile("cp.async.wait_group 0;" ::: "memory")

__device__ __forceinline__ void ldsm4(uint32_t* r, uint32_t addr) {
    asm volatile("ldmatrix.sync.aligned.m8n8.x4.shared.b16 {%0,%1,%2,%3}, [%4];"
                 : "=r"(r[0]), "=r"(r[1]), "=r"(r[2]), "=r"(r[3]) : "r"(addr));
}
__device__ __forceinline__ void mma16816(float* d, const uint32_t* a, uint32_t b0, uint32_t b1) {
    asm volatile("mma.sync.aligned.m16n8k16.row.col.f32.bf16.bf16.f32 "
                 "{%0,%1,%2,%3}, {%4,%5,%6,%7}, {%8,%9}, {%0,%1,%2,%3};"
                 : "+f"(d[0]), "+f"(d[1]), "+f"(d[2]), "+f"(d[3])
                 : "r"(a[0]), "r"(a[1]), "r"(a[2]), "r"(a[3]), "r"(b0), "r"(b1));
}
// fp32x4 -> packed bf16 (RNE)
__device__ __forceinline__ void cvt4(const float4 v, uint32_t& h01, uint32_t& h23) {
    asm("cvt.rn.bf16x2.f32 %0, %1, %2;" : "=r"(h01) : "f"(v.y), "f"(v.x));
    asm("cvt.rn.bf16x2.f32 %0, %1, %2;" : "=r"(h23) : "f"(v.w), "f"(v.z));
}

// ---------------- Kernel 1: codebook bf16 + norms + counter reset ----------
__global__ void prep_kernel(const float* __restrict__ cb) {
    const int c = blockIdx.x;
    const int t = threadIdx.x;                 // 256 threads, one float4 each
    if (c == 0 && t == 0) { g_nflag = 0; g_tick = 0; }
    float4 v = reinterpret_cast<const float4*>(cb + (size_t)c * Hh)[t];
    float s = v.x * v.x + v.y * v.y + v.z * v.z + v.w * v.w;
    uint32_t h01, h23;
    cvt4(v, h01, h23);
    reinterpret_cast<uint2*>(g_chi + (size_t)c * Hh)[t] = make_uint2(h01, h23);
#pragma unroll
    for (int o = 16; o > 0; o >>= 1) s += __shfl_xor_sync(0xffffffffu, s, o);
    __shared__ float ws[8];
    if ((t & 31) == 0) ws[t >> 5] = s;
    __syncthreads();
    if (t == 0) {
        float tot = 0.f;
#pragma unroll
        for (int i = 0; i < 8; i++) tot += ws[i];
        g_csq[c] = tot;
    }
}

// --- Kernel 2: persistent gemm + argmin, prev-tile writeback overlapped ----
// smem per stage: A 64x64 bf16 = 8K | B 256x64 bf16 = 32K
#define STG 40960
#define OFF_A(s) ((s) * STG + 0)
#define OFF_B(s) ((s) * STG + 8192)
#define OFF_CSQ   81920
#define OFF_BV    82944
#define OFF_BI    83968
#define OFF_RMIN  84992
#define OFF_CNT   85248
#define OFF_CAND  85504
#define OFF_TILE  87552
#define OFF_IPREV 87560
#define OFF_MPREV 87816
#define SMEM_TOTAL 88072

__global__ __launch_bounds__(NT, 2)
void vq_gemm(const float* __restrict__ keys, const float* __restrict__ values,
             const float* __restrict__ cb, float* __restrict__ out) {
    extern __shared__ __align__(1024) char smem[];
    const uint32_t sb = smem_u32(smem);
    const int tid  = threadIdx.x;
    const int lane = tid & 31;
    const int wid  = tid >> 5;          // 0..7
    const int wm   = wid >> 2;          // 0..1 (M)
    const int wn   = wid & 3;           // 0..3 (N)

    if (tid < Cc) reinterpret_cast<float*>(smem + OFF_CSQ)[tid] = g_csq[tid];

    const float* csq = reinterpret_cast<const float*>(smem + OFF_CSQ);
    float* bvs   = reinterpret_cast<float*>(smem + OFF_BV);
    int*   bis   = reinterpret_cast<int*>(smem + OFF_BI);
    float* rminv = reinterpret_cast<float*>(smem + OFF_RMIN);
    int*   cnt_s = reinterpret_cast<int*>(smem + OFF_CNT);
    int*   cand  = reinterpret_cast<int*>(smem + OFF_CAND);
    int*   iprev = reinterpret_cast<int*>(smem + OFF_IPREV);
    float* mprev = reinterpret_cast<float*>(smem + OFF_MPREV);
    volatile int* tshare = reinterpret_cast<volatile int*>(smem + OFF_TILE);

    const float4* cbf4 = reinterpret_cast<const float4*>(cb);
    float4* outf4 = reinterpret_cast<float4*>(out);

    const int aRowB = (wm * 32 + (lane & 15)) * 128;              // + mt*2048
    const int aColB = (lane >> 4) * 16;
    const int bRow  = wn * 64 + ((lane >> 4) << 3) + (lane & 7);  // + p*16
    const int bColB = ((lane >> 3) & 1) * 16;

    bool havePrev = false;
    int  prevRowBase = 0;

    while (true) {
        if (tid == 0) *tshare = atomicAdd(&g_tick, 1);
        if (tid < BM) cnt_s[tid] = 0;
        __syncthreads();
        const int tile = *tshare;
        if (tile >= NTILES) break;
        const int rowBase = tile * BM;

        const float* src_base; int srcRow;
        if (rowBase < ROWS_PER_TENSOR) { src_base = keys;   srcRow = rowBase; }
        else                           { src_base = values; srcRow = rowBase - ROWS_PER_TENSOR; }

        float acc[2][8][4];
#pragma unroll
        for (int a = 0; a < 2; a++)
#pragma unroll
            for (int b = 0; b < 8; b++)
#pragma unroll
                for (int k = 0; k < 4; k++) acc[a][b][k] = 0.f;

        auto loadB = [&](int c, int s) {     // 256x64 bf16 = 2048 16B units, 8/thread
#pragma unroll
            for (int i = 0; i < 8; i++) {
                int li = tid + i * NT;
                int row = li >> 3, u = li & 7;
                const __nv_bfloat16* gh = g_chi + (size_t)row * Hh + c * KC + u * 8;
                uint32_t off = swz128((uint32_t)(row * 128 + u * 16));
                cpa16(sb + OFF_B(s) + off, gh);
            }
        };
        auto loadA = [&](float4* pf, int c) {  // 64x64 fp32 = 1024 float4, 4/thread
#pragma unroll
            for (int i = 0; i < 4; i++) {
                int li = tid + i * NT;
                int row = li >> 4, u = li & 15;
                pf[i] = *reinterpret_cast<const float4*>(
                    src_base + (size_t)(srcRow + row) * Hh + c * KC + u * 4);
            }
        };
        auto storeA = [&](const float4* pf, int s) {
#pragma unroll
            for (int i = 0; i < 4; i++) {
                int li = tid + i * NT;
                int row = li >> 4, u = li & 15;
                uint32_t h01, h23;
                cvt4(pf[i], h01, h23);
                uint32_t off = swz128((uint32_t)(row * 128 + u * 8));
                *reinterpret_cast<uint2*>(smem + OFF_A(s) + off) = make_uint2(h01, h23);
            }
        };

        float4 pf[4];
        loadB(0, 0); CP_COMMIT();
        loadA(pf, 0);
        storeA(pf, 0);
        CP_WAIT0();
        __syncthreads();

        for (int c = 0; c < NCHUNK; c++) {
            const int s = c & 1;
            if (c + 1 < NCHUNK) { loadB(c + 1, s ^ 1); CP_COMMIT(); loadA(pf, c + 1); }

            const uint32_t aS = sb + OFF_A(s), bS = sb + OFF_B(s);
#pragma unroll
            for (int ks = 0; ks < 4; ks++) {
                uint32_t ah[2][4];
#pragma unroll
                for (int mt = 0; mt < 2; mt++)
                    ldsm4(ah[mt], aS + swz128((uint32_t)(aRowB + mt * 2048 + ks * 32 + aColB)));
#pragma unroll
                for (int p = 0; p < 4; p++) {
                    uint32_t bh[4];
                    ldsm4(bh, bS + swz128((uint32_t)((bRow + p * 16) * 128 + ks * 32 + bColB)));
#pragma unroll
                    for (int mt = 0; mt < 2; mt++) {
                        mma16816(acc[mt][2 * p],     ah[mt], bh[0], bh[1]);
                        mma16816(acc[mt][2 * p + 1], ah[mt], bh[2], bh[3]);
                    }
                }
            }
            // overlapped writeback: 4 rows of the PREVIOUS tile per chunk
            if (havePrev) {
#pragma unroll
                for (int i = 0; i < 4; i++) {
                    int li = tid + i * NT;           // 0..1023
                    int r  = (c << 2) + (li >> 8);   // 4 rows per chunk
                    int u  = li & 255;
                    int ci = iprev[r];
                    float m = mprev[r];
                    float4 v = __ldg(cbf4 + (size_t)ci * 256 + u);
                    v.x *= m; v.y *= m; v.z *= m; v.w *= m;
                    __stcs(outf4 + (size_t)(prevRowBase + r) * 256 + u, v);
                }
            }
            if (c + 1 < NCHUNK) { storeA(pf, s ^ 1); CP_WAIT0(); }
            __syncthreads();
        }

        // ---- epilogue: scores, per-row argmin, candidates ----
        float mv[4]; int mi[4];
#pragma unroll
        for (int q = 0; q < 4; q++) { mv[q] = __int_as_float(0x7f800000); mi[q] = 0x7fffffff; }
#pragma unroll
        for (int mt = 0; mt < 2; mt++)
#pragma unroll
            for (int nt = 0; nt < 8; nt++) {
                int n0 = wn * 64 + nt * 8 + (lane & 3) * 2;
                float cq0 = csq[n0], cq1 = csq[n0 + 1];
                float s0 = cq0 - 2.f * acc[mt][nt][0];
                float s1 = cq1 - 2.f * acc[mt][nt][1];
                float s2 = cq0 - 2.f * acc[mt][nt][2];
                float s3 = cq1 - 2.f * acc[mt][nt][3];
                int q0 = mt * 2, q1 = mt * 2 + 1;
                if (s0 < mv[q0]) { mv[q0] = s0; mi[q0] = n0; }
                if (s1 < mv[q0]) { mv[q0] = s1; mi[q0] = n0 + 1; }
                if (s2 < mv[q1]) { mv[q1] = s2; mi[q1] = n0; }
                if (s3 < mv[q1]) { mv[q1] = s3; mi[q1] = n0 + 1; }
            }
#pragma unroll
        for (int o = 1; o < 4; o <<= 1)
#pragma unroll
            for (int q = 0; q < 4; q++) {
                float ov = __shfl_xor_sync(0xffffffffu, mv[q], o);
                int   oi = __shfl_xor_sync(0xffffffffu, mi[q], o);
                if (ov < mv[q] || (ov == mv[q] && oi < mi[q])) { mv[q] = ov; mi[q] = oi; }
            }
        if ((lane & 3) == 0) {
#pragma unroll
            for (int q = 0; q < 4; q++) {
                int r = wm * 32 + (q >> 1) * 16 + (lane >> 2) + (q & 1) * 8;
                bvs[r * 4 + wn] = mv[q];
                bis[r * 4 + wn] = mi[q];
            }
        }
        __syncthreads();
        if (tid < BM) {
            float bv = bvs[tid * 4]; int bi = bis[tid * 4];
#pragma unroll
            for (int w = 1; w < 4; w++) {
                float v = bvs[tid * 4 + w]; int i = bis[tid * 4 + w];
                if (v < bv || (v == bv && i < bi)) { bv = v; bi = i; }
            }
            rminv[tid] = bv;
            iprev[tid] = bi;                              // queue for overlapped wb
            mprev[tid] = (csq[bi] > 0.01f) ? 1.0f : 0.0f; // ||c|| > 0.1
        }
        __syncthreads();
        // candidate scan: any score within MARGIN of the row min -> exact recheck
#pragma unroll
        for (int mt = 0; mt < 2; mt++) {
            int rA = wm * 32 + mt * 16 + (lane >> 2);
            float thA = rminv[rA] + MARGIN;
            float thB = rminv[rA + 8] + MARGIN;
#pragma unroll
            for (int nt = 0; nt < 8; nt++) {
                int n0 = wn * 64 + nt * 8 + (lane & 3) * 2;
                float cq0 = csq[n0], cq1 = csq[n0 + 1];
                float s0 = cq0 - 2.f * acc[mt][nt][0];
                float s1 = cq1 - 2.f * acc[mt][nt][1];
                float s2 = cq0 - 2.f * acc[mt][nt][2];
                float s3 = cq1 - 2.f * acc[mt][nt][3];
                if (s0 <= thA) { int p = atomicAdd(&cnt_s[rA], 1);     if (p < 8) cand[rA * 8 + p] = n0; }
                if (s1 <= thA) { int p = atomicAdd(&cnt_s[rA], 1);     if (p < 8) cand[rA * 8 + p] = n0 + 1; }
                if (s2 <= thB) { int p = atomicAdd(&cnt_s[rA + 8], 1); if (p < 8) cand[(rA + 8) * 8 + p] = n0; }
                if (s3 <= thB) { int p = atomicAdd(&cnt_s[rA + 8], 1); if (p < 8) cand[(rA + 8) * 8 + p] = n0 + 1; }
            }
        }
        __syncthreads();
        if (tid < BM && cnt_s[tid] > 1) {   // ambiguous under bf16 noise -> exact fixup
            int gi = atomicAdd(&g_nflag, 1);
            g_frow[gi] = rowBase + tid;
            int cc = cnt_s[tid] <= 8 ? cnt_s[tid] : 0;   // 0 => recompute all 256
            g_fcnt[gi] = cc;
            for (int j = 0; j < cc; j++) g_fcand[gi][j] = cand[tid * 8 + j];
        }
        havePrev = true;
        prevRowBase = rowBase;
        __syncthreads();   // protect cnt_s/cand/rminv/iprev reuse by next tile
    }

    // drain: final tile's writeback (no successor tile to overlap into)
    if (havePrev) {
        for (int i = tid; i < BM * 256; i += NT) {
            int r = i >> 8;
            int u = i & 255;
            int ci = iprev[r];
            float m = mprev[r];
            float4 v = __ldg(cbf4 + (size_t)ci * 256 + u);
            v.x *= m; v.y *= m; v.z *= m; v.w *= m;
            __stcs(outf4 + (size_t)(prevRowBase + r) * 256 + u, v);
        }
    }
}

// ------- Kernel 3: exact fp32 fixup for flagged rows (rewrites rows) -------
__global__ void fixup_kernel(const float* __restrict__ keys, const float* __restrict__ values,
                             const float* __restrict__ cb, float* __restrict__ out) {
    const int nflag = g_nflag;
    const int lane  = threadIdx.x & 31;
    const int warp  = (blockIdx.x * blockDim.x + threadIdx.x) >> 5;
    const int nwarp = (gridDim.x * blockDim.x) >> 5;

    for (int e = warp; e < nflag; e += nwarp) {
        int row = g_frow[e];
        int cc  = g_fcnt[e];
        const float4* xr = reinterpret_cast<const float4*>(
            row < ROWS_PER_TENSOR ? keys + (size_t)row * Hh
                                  : values + (size_t)(row - ROWS_PER_TENSOR) * Hh);
        float4 xa[8];
#pragma unroll
        for (int t = 0; t < 8; t++) xa[t] = xr[lane + 32 * t];
        int ncand = (cc == 0) ? Cc : cc;
        float bv = __int_as_float(0x7f800000);
        int   bi = 0x7fffffff;
        for (int j = 0; j < ncand; j++) {
            int c = (cc == 0) ? j : g_fcand[e][j];
            const float4* cr = reinterpret_cast<const float4*>(cb + (size_t)c * Hh);
            float d = 0.f;
#pragma unroll
            for (int t = 0; t < 8; t++) {
                float4 b = cr[lane + 32 * t];
                d += xa[t].x * b.x + xa[t].y * b.y + xa[t].z * b.z + xa[t].w * b.w;
            }
#pragma unroll
            for (int o = 16; o > 0; o >>= 1) d += __shfl_xor_sync(0xffffffffu, d, o);
            float sc = g_csq[c] - 2.f * d;
            if (sc < bv || (sc == bv && c < bi)) { bv = sc; bi = c; }
        }
        float m = (g_csq[bi] > 0.01f) ? 1.0f : 0.0f;
        const float4* cr = reinterpret_cast<const float4*>(cb + (size_t)bi * Hh);
        float4* orow = reinterpret_cast<float4*>(out + (size_t)row * Hh);
#pragma unroll
        for (int t = 0; t < 8; t++) {
            float4 v = cr[lane + 32 * t];
            v.x *= m; v.y *= m; v.z *= m; v.w *= m;
            orow[lane + 32 * t] = v;
        }
    }
}

extern "C" void kernel_launch(void* const* d_in, const int* in_sizes, int n_in,
                              void* d_out, int out_size) {
    const float* keys     = (const float*)d_in[0];
    const float* values   = (const float*)d_in[1];
    const float* codebook = (const float*)d_in[2];
    float* out = (float*)d_out;

    cudaFuncSetAttribute(vq_gemm, cudaFuncAttributeMaxDynamicSharedMemorySize, SMEM_TOTAL);
    prep_kernel<<<Cc, 256>>>(codebook);
    vq_gemm<<<NCTA, NT, SMEM_TOTAL>>>(keys, values, codebook, out);
    fixup_kernel<<<148, 256>>>(keys, values, codebook, out);
}